// round 7
// baseline (speedup 1.0000x reference)
#include <cuda_runtime.h>
#include <math.h>

#define BB   8192
#define INF  512
#define OUTF 1024
#define KWID 1535   // weight row length (IN_F + OUT_F - 1)
#define CB   64
#define NBLK (OUTF / CB)
#define TT   4      // slot-threads per row
#define SL   16     // slots (columns) per thread  (CB/TT)

// Column-major fp32 buffers: [col * BB + row]
__device__ float g_XW[(size_t)BB * OUTF];  // x @ Wx^T + bias (ref chain order)
__device__ float g_D [(size_t)BB * OUTF];  // prefix dot chain sum_{j<base} out_j*Wo[col,j]

// ---------------------------------------------------------------------------
// Packed dual fp32 FMA: two independent IEEE-RN fp32 FMAs per issue.
// Each half is bit-identical to FFMA => chain values unchanged.
// ---------------------------------------------------------------------------
__device__ __forceinline__ unsigned long long ffma2(unsigned long long a,
                                                    unsigned long long b,
                                                    unsigned long long c)
{
    unsigned long long d;
    asm("fma.rn.f32x2 %0, %1, %2, %3;" : "=l"(d) : "l"(a), "l"(b), "l"(c));
    return d;
}

__device__ __forceinline__ float f2lo(unsigned long long v)
{ return __uint_as_float((unsigned)(v & 0xffffffffULL)); }
__device__ __forceinline__ float f2hi(unsigned long long v)
{ return __uint_as_float((unsigned)(v >> 32)); }

// ---------------------------------------------------------------------------
// XLA-faithful fp32 logistic: 0.5*fast_tanh(0.5*x) + 0.5 (EmitFastTanh
// rational approx). All mul/add UNFUSED, matching XLA's raw FMul/FAdd.
// ---------------------------------------------------------------------------
__device__ __forceinline__ float xla_fast_tanh(float x)
{
    float ax = fabsf(x);
    float xc = fminf(fmaxf(x, -7.90531110763549805f), 7.90531110763549805f);
    float x2 = __fmul_rn(xc, xc);
    float np = __fadd_rn(__fmul_rn(x2, -2.76076847742355e-16f), 2.00018790482477e-13f);
    np = __fadd_rn(__fmul_rn(x2, np), -8.60467152213735e-11f);
    np = __fadd_rn(__fmul_rn(x2, np),  5.12229709037114e-08f);
    np = __fadd_rn(__fmul_rn(x2, np),  1.48572235717979e-05f);
    np = __fadd_rn(__fmul_rn(x2, np),  6.37261928875436e-04f);
    np = __fadd_rn(__fmul_rn(x2, np),  4.89352455891786e-03f);
    np = __fmul_rn(xc, np);
    float dq = __fadd_rn(__fmul_rn(x2, 1.19825839466702e-06f), 1.18534705686654e-04f);
    dq = __fadd_rn(__fmul_rn(x2, dq), 2.26843463243900e-03f);
    dq = __fadd_rn(__fmul_rn(x2, dq), 4.89352518554385e-03f);
    float r = __fdiv_rn(np, dq);
    return (ax < 0.0004f) ? x : r;
}

__device__ __forceinline__ float xla_logistic_f32(float x)
{
    float t = xla_fast_tanh(__fmul_rn(0.5f, x));
    return __fadd_rn(__fmul_rn(0.5f, t), 0.5f);
}

// ---------------------------------------------------------------------------
// GEMM: dst[col][m] = chain_{k} fma(A[m][k], W[col*KWID+koff+k]) (+bias)
// Per output element: ONE fp32 accumulator, strict ascending-k FMA chain
// (bit-matches Eigen gebp). 64x64 tile, BK=16, 256 threads, 4x4 microtile.
// FFMA2 packed along the row (i) axis: acc pairs (2p,2p+1); B duplicated in
// smem so LDS.128 yields splat pairs (b,b) with zero pack instructions.
// mode 0: + bias -> g_XW.   mode 1: raw chain -> g_D.
// ---------------------------------------------------------------------------
__global__ void __launch_bounds__(256)
gemm_kernel(const float* __restrict__ A, const float* __restrict__ W,
            const float* __restrict__ bias, float* __restrict__ dst,
            int K, int nbase0, int koff, int lda, int mode)
{
    __shared__ __align__(16) float As[16][68];
    __shared__ __align__(16) float Bs[16][132];   // duplicated: [2n]=[2n+1]=b_n
    const int tid   = threadIdx.x;
    const int m0    = blockIdx.x * 64;
    const int nbase = nbase0 + blockIdx.y * 64;
    const int tx = tid & 15;          // col group: cols tx*4..tx*4+3
    const int ty = tid >> 4;          // row group: rows ty*4..ty*4+3
    const int am = tid >> 2;
    const int ak = (tid & 3) << 2;
    const int bk = tid & 15;
    const int bn = tid >> 4;

    unsigned long long acc2[2][4];    // acc2[p][j] = rows (ty*4+2p, +2p+1), col tx*4+j
#pragma unroll
    for (int p = 0; p < 2; ++p)
#pragma unroll
        for (int j = 0; j < 4; ++j) acc2[p][j] = 0ULL;

    const float* Arow  = A + (size_t)(m0 + am) * lda + ak;
    const float* Wbase = W + (size_t)koff;

    for (int k0 = 0; k0 < K; k0 += 16) {
        float4 av = *reinterpret_cast<const float4*>(Arow + k0);
        As[ak + 0][am] = av.x;
        As[ak + 1][am] = av.y;
        As[ak + 2][am] = av.z;
        As[ak + 3][am] = av.w;
#pragma unroll
        for (int q = 0; q < 4; ++q) {
            int n = bn + q * 16;
            float v = Wbase[(size_t)(nbase + n) * KWID + k0 + bk];
            Bs[bk][2 * n]     = v;
            Bs[bk][2 * n + 1] = v;
        }
        __syncthreads();
#pragma unroll
        for (int kk = 0; kk < 16; ++kk) {
            ulonglong2 a2 = *reinterpret_cast<const ulonglong2*>(&As[kk][ty << 2]);
            ulonglong2 b0 = *reinterpret_cast<const ulonglong2*>(&Bs[kk][tx << 3]);
            ulonglong2 b1 = *reinterpret_cast<const ulonglong2*>(&Bs[kk][(tx << 3) + 4]);
            acc2[0][0] = ffma2(a2.x, b0.x, acc2[0][0]);
            acc2[1][0] = ffma2(a2.y, b0.x, acc2[1][0]);
            acc2[0][1] = ffma2(a2.x, b0.y, acc2[0][1]);
            acc2[1][1] = ffma2(a2.y, b0.y, acc2[1][1]);
            acc2[0][2] = ffma2(a2.x, b1.x, acc2[0][2]);
            acc2[1][2] = ffma2(a2.y, b1.x, acc2[1][2]);
            acc2[0][3] = ffma2(a2.x, b1.y, acc2[0][3]);
            acc2[1][3] = ffma2(a2.y, b1.y, acc2[1][3]);
        }
        __syncthreads();
    }

#pragma unroll
    for (int j = 0; j < 4; ++j) {
        int col = nbase + (tx << 2) + j;
        float* d = dst + (size_t)col * BB + m0 + (ty << 2);
        float4 v;
        v.x = f2lo(acc2[0][j]);
        v.y = f2hi(acc2[0][j]);
        v.z = f2lo(acc2[1][j]);
        v.w = f2hi(acc2[1][j]);
        if (mode == 0) {
            float bv = bias[col];
            v.x = __fadd_rn(v.x, bv);
            v.y = __fadd_rn(v.y, bv);
            v.z = __fadd_rn(v.z, bv);
            v.w = __fadd_rn(v.w, bv);
        }
        *reinterpret_cast<float4*>(d) = v;
    }
}

// ---------------------------------------------------------------------------
// Slot-split sequential sweep (UNCHANGED from R6): 256 threads = 64 rows x 4
// slot-threads; zero-padded triangle makes non-owner FMAs exact no-ops, so
// per-column chains stay bit-identical to the reference order.
// ---------------------------------------------------------------------------
__global__ void __launch_bounds__(256)
seq_kernel(int base, const float* __restrict__ W, const float* __restrict__ U,
           float* __restrict__ out, float* __restrict__ Lout)
{
    __shared__ __align__(16) float tri[CB][CB + 4]; // tri[i][j], 0 for j<=i
    __shared__ __align__(16) float stg[CB][CB + 4]; // staging: logits, then samples
    const int tid  = threadIdx.x;       // 256
    const int r0   = blockIdx.x * CB;
    const int rl   = tid >> 2;          // row 0..63
    const int t    = tid & 3;           // slot group 0..3
    const int r    = r0 + rl;
    const int lane = tid & 31;

#pragma unroll 1
    for (int idx = tid; idx < CB * CB; idx += 256) {
        int i = idx & (CB - 1);
        int j = idx >> 6;
        float v = 0.0f;
        if (j > i) v = W[(size_t)(base + j) * KWID + INF + base + i];
        tri[i][j] = v;
    }
    __syncthreads();

    float ureg[SL], xwreg[SL], accf[SL], logits[SL];
    {
        const float* Urow = U + (size_t)r * OUTF + base + (t << 4);
#pragma unroll
        for (int m = 0; m < SL; m += 4) {
            float4 v = *reinterpret_cast<const float4*>(Urow + m);
            ureg[m] = v.x; ureg[m+1] = v.y; ureg[m+2] = v.z; ureg[m+3] = v.w;
        }
    }
#pragma unroll
    for (int m = 0; m < SL; ++m)
        xwreg[m] = g_XW[(size_t)(base + (t << 4) + m) * BB + r];
    if (base == 0) {
#pragma unroll
        for (int m = 0; m < SL; ++m) accf[m] = 0.0f;
    } else {
#pragma unroll
        for (int m = 0; m < SL; ++m)
            accf[m] = g_D[(size_t)(base + (t << 4) + m) * BB + r];
    }

    unsigned smask = 0u;
    const float* tbase = &tri[0][0] + (t << 4);

#pragma unroll 1
    for (int g = 0; g < TT; ++g) {
        const int src = (lane & ~3) | g;
#pragma unroll
        for (int m = 0; m < SL; ++m) {
            const int i = (g << 4) + m;
            float cand = __fadd_rn(xwreg[m], accf[m]);
            float p    = xla_logistic_f32(cand);
            float sc   = (ureg[m] < p) ? 1.0f : 0.0f;
            float s    = __shfl_sync(0xffffffffu, sc, src);
            if (t == g) {
                logits[m] = cand;
                smask |= (sc != 0.0f ? 1u : 0u) << m;
            }
            const float* trow = tbase + i * (CB + 4);
#pragma unroll
            for (int mm = 0; mm < SL; mm += 4) {
                float4 tv = *reinterpret_cast<const float4*>(trow + mm);
                accf[mm + 0] = fmaf(s, tv.x, accf[mm + 0]);
                accf[mm + 1] = fmaf(s, tv.y, accf[mm + 1]);
                accf[mm + 2] = fmaf(s, tv.z, accf[mm + 2]);
                accf[mm + 3] = fmaf(s, tv.w, accf[mm + 3]);
            }
        }
    }

#pragma unroll
    for (int m = 0; m < SL; m += 4) {
        float4 v; v.x = logits[m]; v.y = logits[m+1]; v.z = logits[m+2]; v.w = logits[m+3];
        *reinterpret_cast<float4*>(&stg[rl][(t << 4) + m]) = v;
    }
    __syncthreads();
#pragma unroll 1
    for (int idx = tid; idx < CB * CB; idx += 256) {
        int rr = idx >> 6, c = idx & (CB - 1);
        Lout[(size_t)(r0 + rr) * OUTF + base + c] = stg[rr][c];
    }
    __syncthreads();
#pragma unroll
    for (int m = 0; m < SL; m += 4) {
        float4 v;
        v.x = (float)((smask >> (m + 0)) & 1u);
        v.y = (float)((smask >> (m + 1)) & 1u);
        v.z = (float)((smask >> (m + 2)) & 1u);
        v.w = (float)((smask >> (m + 3)) & 1u);
        *reinterpret_cast<float4*>(&stg[rl][(t << 4) + m]) = v;
    }
    __syncthreads();
#pragma unroll 1
    for (int idx = tid; idx < CB * CB; idx += 256) {
        int rr = idx >> 6, c = idx & (CB - 1);
        out[(size_t)(r0 + rr) * OUTF + base + c] = stg[rr][c];
    }
}

// ---------------------------------------------------------------------------
// Launch: xw GEMM, then 16 x (prefix block GEMM + sweep).
// d_out: [out][logits], both B*OUT_F fp32.
// ---------------------------------------------------------------------------
extern "C" void kernel_launch(void* const* d_in, const int* in_sizes, int n_in,
                              void* d_out, int out_size)
{
    const float* x    = (const float*)d_in[0];
    const float* w    = (const float*)d_in[1];
    const float* bias = (const float*)d_in[2];
    const float* u    = (const float*)d_in[3];
    float* out  = (float*)d_out;
    float* Lout = out + (size_t)BB * OUTF;

    float* xw_ptr;  cudaGetSymbolAddress((void**)&xw_ptr, g_XW);
    float* d_ptr;   cudaGetSymbolAddress((void**)&d_ptr,  g_D);

    gemm_kernel<<<dim3(BB / 64, OUTF / 64), 256>>>(x, w, bias, xw_ptr,
                                                   INF, 0, 0, INF, 0);
    for (int k = 0; k < NBLK; ++k) {
        int base = k * CB;
        if (k > 0)
            gemm_kernel<<<dim3(BB / 64, 1), 256>>>(out, w, bias, d_ptr,
                                                   base, base, INF, OUTF, 1);
        seq_kernel<<<BB / CB, 256>>>(base, w, u, out, Lout);
    }
}

// round 8
// speedup vs baseline: 1.7124x; 1.7124x over previous
#include <cuda_runtime.h>
#include <math.h>

#define BB   8192
#define INF  512
#define OUTF 1024
#define KWID 1535   // weight row length (IN_F + OUT_F - 1)
#define CB   64
#define NBLK (OUTF / CB)
#define TT   4      // slot-threads per row
#define SL   16     // slots (columns) per thread  (CB/TT)

// Column-major fp32 buffers: [col * BB + row]
__device__ float g_XW[(size_t)BB * OUTF];  // x @ Wx^T + bias (ref chain order)
__device__ float g_D [(size_t)BB * OUTF];  // prefix dot chain sum_{j<base} out_j*Wo[col,j]

// ---------------------------------------------------------------------------
// XLA-faithful fp32 logistic: 0.5*fast_tanh(0.5*x) + 0.5 (EmitFastTanh
// rational approx). All mul/add UNFUSED, matching XLA's raw FMul/FAdd.
// ---------------------------------------------------------------------------
__device__ __forceinline__ float xla_fast_tanh(float x)
{
    float ax = fabsf(x);
    float xc = fminf(fmaxf(x, -7.90531110763549805f), 7.90531110763549805f);
    float x2 = __fmul_rn(xc, xc);
    float np = __fadd_rn(__fmul_rn(x2, -2.76076847742355e-16f), 2.00018790482477e-13f);
    np = __fadd_rn(__fmul_rn(x2, np), -8.60467152213735e-11f);
    np = __fadd_rn(__fmul_rn(x2, np),  5.12229709037114e-08f);
    np = __fadd_rn(__fmul_rn(x2, np),  1.48572235717979e-05f);
    np = __fadd_rn(__fmul_rn(x2, np),  6.37261928875436e-04f);
    np = __fadd_rn(__fmul_rn(x2, np),  4.89352455891786e-03f);
    np = __fmul_rn(xc, np);
    float dq = __fadd_rn(__fmul_rn(x2, 1.19825839466702e-06f), 1.18534705686654e-04f);
    dq = __fadd_rn(__fmul_rn(x2, dq), 2.26843463243900e-03f);
    dq = __fadd_rn(__fmul_rn(x2, dq), 4.89352518554385e-03f);
    float r = __fdiv_rn(np, dq);
    return (ax < 0.0004f) ? x : r;
}

__device__ __forceinline__ float xla_logistic_f32(float x)
{
    float t = xla_fast_tanh(__fmul_rn(0.5f, x));
    return __fadd_rn(__fmul_rn(0.5f, t), 0.5f);
}

// ---------------------------------------------------------------------------
// GEMM (R6 scalar-FFMA body): per output element ONE fp32 accumulator,
// strict ascending-k FMA chain (bit-matches Eigen gebp). 64x64 tile, BK=16,
// 256 threads, 4x4 microtile. Column-major dst [col*BB + row].
// mode 0: acc=0, dst = acc + bias        (xw blocks -> g_XW)
// mode 1: acc=0, dst = acc               (first-touch D contribution)
// mode 2: acc preloaded FROM dst, chain continues, dst = acc  (RMW D).
//         Preload-then-chain == reference's single running accumulator:
//         the store/reload rounds nothing, order is preserved exactly.
// ---------------------------------------------------------------------------
__global__ void __launch_bounds__(256)
gemm_kernel(const float* __restrict__ A, const float* __restrict__ W,
            const float* __restrict__ bias, float* __restrict__ dst,
            int K, int nbase0, int koff, int lda, int mode)
{
    __shared__ float As[16][68];
    __shared__ float Bs[16][68];
    const int tid   = threadIdx.x;
    const int m0    = blockIdx.x * 64;
    const int nbase = nbase0 + blockIdx.y * 64;
    const int tx = tid & 15;
    const int ty = tid >> 4;
    const int am = tid >> 2;
    const int ak = (tid & 3) << 2;
    const int bk = tid & 15;
    const int bn = tid >> 4;

    float acc[4][4];
    if (mode == 2) {
#pragma unroll
        for (int j = 0; j < 4; ++j) {
            int col = nbase + (tx << 2) + j;
            float4 o = *reinterpret_cast<const float4*>(
                dst + (size_t)col * BB + m0 + (ty << 2));
            acc[0][j] = o.x; acc[1][j] = o.y; acc[2][j] = o.z; acc[3][j] = o.w;
        }
    } else {
#pragma unroll
        for (int i = 0; i < 4; ++i)
#pragma unroll
            for (int j = 0; j < 4; ++j) acc[i][j] = 0.0f;
    }

    const float* Arow  = A + (size_t)(m0 + am) * lda + ak;
    const float* Wbase = W + (size_t)koff;

    for (int k0 = 0; k0 < K; k0 += 16) {
        float4 av = *reinterpret_cast<const float4*>(Arow + k0);
        As[ak + 0][am] = av.x;
        As[ak + 1][am] = av.y;
        As[ak + 2][am] = av.z;
        As[ak + 3][am] = av.w;
#pragma unroll
        for (int q = 0; q < 4; ++q) {
            int n = bn + q * 16;
            Bs[bk][n] = Wbase[(size_t)(nbase + n) * KWID + k0 + bk];
        }
        __syncthreads();
#pragma unroll
        for (int kk = 0; kk < 16; ++kk) {
            float4 a4 = *reinterpret_cast<const float4*>(&As[kk][ty << 2]);
            float4 b4 = *reinterpret_cast<const float4*>(&Bs[kk][tx << 2]);
            float a[4] = {a4.x, a4.y, a4.z, a4.w};
            float b[4] = {b4.x, b4.y, b4.z, b4.w};
#pragma unroll
            for (int i = 0; i < 4; ++i)
#pragma unroll
                for (int j = 0; j < 4; ++j)
                    acc[i][j] = fmaf(a[i], b[j], acc[i][j]);
        }
        __syncthreads();
    }

#pragma unroll
    for (int j = 0; j < 4; ++j) {
        int col = nbase + (tx << 2) + j;
        float* d = dst + (size_t)col * BB + m0 + (ty << 2);
        float4 v;
        v.x = acc[0][j]; v.y = acc[1][j]; v.z = acc[2][j]; v.w = acc[3][j];
        if (mode == 0) {
            float bv = bias[col];
            v.x = __fadd_rn(v.x, bv);
            v.y = __fadd_rn(v.y, bv);
            v.z = __fadd_rn(v.z, bv);
            v.w = __fadd_rn(v.w, bv);
        }
        *reinterpret_cast<float4*>(d) = v;
    }
}

// ---------------------------------------------------------------------------
// Slot-split sequential sweep (UNCHANGED from R6).
// ---------------------------------------------------------------------------
__global__ void __launch_bounds__(256)
seq_kernel(int base, const float* __restrict__ W, const float* __restrict__ U,
           float* __restrict__ out, float* __restrict__ Lout)
{
    __shared__ __align__(16) float tri[CB][CB + 4]; // tri[i][j], 0 for j<=i
    __shared__ __align__(16) float stg[CB][CB + 4];
    const int tid  = threadIdx.x;
    const int r0   = blockIdx.x * CB;
    const int rl   = tid >> 2;
    const int t    = tid & 3;
    const int r    = r0 + rl;
    const int lane = tid & 31;

#pragma unroll 1
    for (int idx = tid; idx < CB * CB; idx += 256) {
        int i = idx & (CB - 1);
        int j = idx >> 6;
        float v = 0.0f;
        if (j > i) v = W[(size_t)(base + j) * KWID + INF + base + i];
        tri[i][j] = v;
    }
    __syncthreads();

    float ureg[SL], xwreg[SL], accf[SL], logits[SL];
    {
        const float* Urow = U + (size_t)r * OUTF + base + (t << 4);
#pragma unroll
        for (int m = 0; m < SL; m += 4) {
            float4 v = *reinterpret_cast<const float4*>(Urow + m);
            ureg[m] = v.x; ureg[m+1] = v.y; ureg[m+2] = v.z; ureg[m+3] = v.w;
        }
    }
#pragma unroll
    for (int m = 0; m < SL; ++m)
        xwreg[m] = g_XW[(size_t)(base + (t << 4) + m) * BB + r];
    if (base == 0) {
#pragma unroll
        for (int m = 0; m < SL; ++m) accf[m] = 0.0f;
    } else {
#pragma unroll
        for (int m = 0; m < SL; ++m)
            accf[m] = g_D[(size_t)(base + (t << 4) + m) * BB + r];
    }

    unsigned smask = 0u;
    const float* tbase = &tri[0][0] + (t << 4);

#pragma unroll 1
    for (int g = 0; g < TT; ++g) {
        const int src = (lane & ~3) | g;
#pragma unroll
        for (int m = 0; m < SL; ++m) {
            const int i = (g << 4) + m;
            float cand = __fadd_rn(xwreg[m], accf[m]);
            float p    = xla_logistic_f32(cand);
            float sc   = (ureg[m] < p) ? 1.0f : 0.0f;
            float s    = __shfl_sync(0xffffffffu, sc, src);
            if (t == g) {
                logits[m] = cand;
                smask |= (sc != 0.0f ? 1u : 0u) << m;
            }
            const float* trow = tbase + i * (CB + 4);
#pragma unroll
            for (int mm = 0; mm < SL; mm += 4) {
                float4 tv = *reinterpret_cast<const float4*>(trow + mm);
                accf[mm + 0] = fmaf(s, tv.x, accf[mm + 0]);
                accf[mm + 1] = fmaf(s, tv.y, accf[mm + 1]);
                accf[mm + 2] = fmaf(s, tv.z, accf[mm + 2]);
                accf[mm + 3] = fmaf(s, tv.w, accf[mm + 3]);
            }
        }
    }

#pragma unroll
    for (int m = 0; m < SL; m += 4) {
        float4 v; v.x = logits[m]; v.y = logits[m+1]; v.z = logits[m+2]; v.w = logits[m+3];
        *reinterpret_cast<float4*>(&stg[rl][(t << 4) + m]) = v;
    }
    __syncthreads();
#pragma unroll 1
    for (int idx = tid; idx < CB * CB; idx += 256) {
        int rr = idx >> 6, c = idx & (CB - 1);
        Lout[(size_t)(r0 + rr) * OUTF + base + c] = stg[rr][c];
    }
    __syncthreads();
#pragma unroll
    for (int m = 0; m < SL; m += 4) {
        float4 v;
        v.x = (float)((smask >> (m + 0)) & 1u);
        v.y = (float)((smask >> (m + 1)) & 1u);
        v.z = (float)((smask >> (m + 2)) & 1u);
        v.w = (float)((smask >> (m + 3)) & 1u);
        *reinterpret_cast<float4*>(&stg[rl][(t << 4) + m]) = v;
    }
    __syncthreads();
#pragma unroll 1
    for (int idx = tid; idx < CB * CB; idx += 256) {
        int rr = idx >> 6, c = idx & (CB - 1);
        out[(size_t)(r0 + rr) * OUTF + base + c] = stg[rr][c];
    }
}

// ---------------------------------------------------------------------------
// Multi-stream DAG (capture-safe fork/join with events):
//  s2: xw blocks 1..15 serially (read-only producers for sweeps).
//  s0 (main): xw0 -> sweep0 -> updN0 -> sweep1 -> updN1 -> ... -> sweep15
//  s1: updR(k) after sweep(k): bulk D update of blocks k+2..15.
//  Exact chain order per column c (block m): updR(0) < ... < updR(m-2)
//  (s1 serial) < updN(m-1) (waits eUpdR[m-2]) — ascending block order, each
//  kernel chaining 64 FMAs onto the preloaded accumulator.
// ---------------------------------------------------------------------------
extern "C" void kernel_launch(void* const* d_in, const int* in_sizes, int n_in,
                              void* d_out, int out_size)
{
    const float* x    = (const float*)d_in[0];
    const float* w    = (const float*)d_in[1];
    const float* bias = (const float*)d_in[2];
    const float* u    = (const float*)d_in[3];
    float* out  = (float*)d_out;
    float* Lout = out + (size_t)BB * OUTF;

    float* xw_ptr;  cudaGetSymbolAddress((void**)&xw_ptr, g_XW);
    float* d_ptr;   cudaGetSymbolAddress((void**)&d_ptr,  g_D);

    cudaStream_t s1, s2;
    cudaStreamCreateWithFlags(&s1, cudaStreamNonBlocking);
    cudaStreamCreateWithFlags(&s2, cudaStreamNonBlocking);

    cudaEvent_t eRoot, eXw[NBLK], eSweep[NBLK], eUpdR[NBLK];
    cudaEventCreateWithFlags(&eRoot, cudaEventDisableTiming);
    for (int i = 0; i < NBLK; ++i) {
        cudaEventCreateWithFlags(&eXw[i],   cudaEventDisableTiming);
        cudaEventCreateWithFlags(&eSweep[i],cudaEventDisableTiming);
        cudaEventCreateWithFlags(&eUpdR[i], cudaEventDisableTiming);
    }

    // fork s1/s2 off the capture-origin (legacy) stream
    cudaEventRecord(eRoot, 0);
    cudaStreamWaitEvent(s1, eRoot, 0);
    cudaStreamWaitEvent(s2, eRoot, 0);

    // s2: xw blocks 1..15
    for (int b = 1; b < NBLK; ++b) {
        gemm_kernel<<<dim3(128, 1), 256, 0, s2>>>(x, w, bias, xw_ptr,
                                                  INF, 64 * b, 0, INF, 0);
        cudaEventRecord(eXw[b], s2);
    }

    // s0: xw block 0, sweep 0
    gemm_kernel<<<dim3(128, 1), 256>>>(x, w, bias, xw_ptr, INF, 0, 0, INF, 0);
    seq_kernel<<<128, 256>>>(0, w, u, out, Lout);
    cudaEventRecord(eSweep[0], 0);

    for (int k = 0; k < NBLK - 1; ++k) {
        // s1: bulk update of blocks k+2..15 with block-k samples
        if (k <= NBLK - 3) {
            cudaStreamWaitEvent(s1, eSweep[k], 0);
            gemm_kernel<<<dim3(128, NBLK - 2 - k), 256, 0, s1>>>(
                out + 64 * k, w, bias, d_ptr,
                64, 64 * (k + 2), INF + 64 * k, OUTF, (k == 0) ? 1 : 2);
            cudaEventRecord(eUpdR[k], s1);
        }
        // s0: next-block update with block-k samples (after updR[k-1]!)
        if (k >= 1) cudaStreamWaitEvent(0, eUpdR[k - 1], 0);
        gemm_kernel<<<dim3(128, 1), 256>>>(
            out + 64 * k, w, bias, d_ptr,
            64, 64 * (k + 1), INF + 64 * k, OUTF, (k == 0) ? 1 : 2);
        // s0: sweep block k+1
        cudaStreamWaitEvent(0, eXw[k + 1], 0);
        seq_kernel<<<128, 256>>>(64 * (k + 1), w, u, out, Lout);
        if (k + 1 < NBLK - 1) cudaEventRecord(eSweep[k + 1], 0);
    }
    // s1's last node (updR[13]) is joined via updN(14)'s wait; s2 via eXw[15].

    for (int i = 0; i < NBLK; ++i) {
        cudaEventDestroy(eXw[i]);
        cudaEventDestroy(eSweep[i]);
        cudaEventDestroy(eUpdR[i]);
    }
    cudaEventDestroy(eRoot);
    cudaStreamDestroy(s1);
    cudaStreamDestroy(s2);
}

// round 9
// speedup vs baseline: 1.8521x; 1.0816x over previous
#include <cuda_runtime.h>
#include <math.h>

#define BB   8192
#define INF  512
#define OUTF 1024
#define KWID 1535   // weight row length (IN_F + OUT_F - 1)
#define CB   64
#define NBLK (OUTF / CB)
#define TT   4      // slot-threads per row
#define SL   16     // slots (columns) per thread  (CB/TT)

// Column-major fp32 buffers: [col * BB + row]
__device__ float g_XW[(size_t)BB * OUTF];  // x @ Wx^T + bias (ref chain order)
__device__ float g_D [(size_t)BB * OUTF];  // prefix dot chain sum_{j<base} out_j*Wo[col,j]

// ---------------------------------------------------------------------------
// XLA-faithful fp32 logistic: 0.5*fast_tanh(0.5*x) + 0.5 (EmitFastTanh
// rational approx). All mul/add UNFUSED, matching XLA's raw FMul/FAdd.
// ---------------------------------------------------------------------------
__device__ __forceinline__ float xla_fast_tanh(float x)
{
    float ax = fabsf(x);
    float xc = fminf(fmaxf(x, -7.90531110763549805f), 7.90531110763549805f);
    float x2 = __fmul_rn(xc, xc);
    float np = __fadd_rn(__fmul_rn(x2, -2.76076847742355e-16f), 2.00018790482477e-13f);
    np = __fadd_rn(__fmul_rn(x2, np), -8.60467152213735e-11f);
    np = __fadd_rn(__fmul_rn(x2, np),  5.12229709037114e-08f);
    np = __fadd_rn(__fmul_rn(x2, np),  1.48572235717979e-05f);
    np = __fadd_rn(__fmul_rn(x2, np),  6.37261928875436e-04f);
    np = __fadd_rn(__fmul_rn(x2, np),  4.89352455891786e-03f);
    np = __fmul_rn(xc, np);
    float dq = __fadd_rn(__fmul_rn(x2, 1.19825839466702e-06f), 1.18534705686654e-04f);
    dq = __fadd_rn(__fmul_rn(x2, dq), 2.26843463243900e-03f);
    dq = __fadd_rn(__fmul_rn(x2, dq), 4.89352518554385e-03f);
    float r = __fdiv_rn(np, dq);
    return (ax < 0.0004f) ? x : r;
}

__device__ __forceinline__ float xla_logistic_f32(float x)
{
    float t = xla_fast_tanh(__fmul_rn(0.5f, x));
    return __fadd_rn(__fmul_rn(0.5f, t), 0.5f);
}

// ---------------------------------------------------------------------------
// GEMM, double-buffered: per output element ONE fp32 accumulator, strict
// ascending-k FMA chain (bit-matches Eigen gebp). 64x64 tile, BK=16,
// 256 threads, 4x4 microtile. Column-major dst [col*BB + row].
// Each iteration: prefetch next tile (LDG -> regs), compute current tile
// from smem, store prefetched tile, ONE sync. LDG->use distance = full
// compute block => latency hidden even at 1 block/SM (slim launches).
// mode 0: acc=0, dst = acc + bias        (xw blocks -> g_XW)
// mode 1: acc=0, dst = acc               (first-touch D contribution)
// mode 2: acc preloaded FROM dst, chain continues, dst = acc  (RMW D).
// ---------------------------------------------------------------------------
__global__ void __launch_bounds__(256)
gemm_kernel(const float* __restrict__ A, const float* __restrict__ W,
            const float* __restrict__ bias, float* __restrict__ dst,
            int K, int nbase0, int koff, int lda, int mode)
{
    __shared__ float As[2][16][68];
    __shared__ float Bs[2][16][68];
    const int tid   = threadIdx.x;
    const int m0    = blockIdx.x * 64;
    const int nbase = nbase0 + blockIdx.y * 64;
    const int tx = tid & 15;
    const int ty = tid >> 4;
    const int am = tid >> 2;
    const int ak = (tid & 3) << 2;
    const int bk = tid & 15;
    const int bn = tid >> 4;

    float acc[4][4];
    if (mode == 2) {
#pragma unroll
        for (int j = 0; j < 4; ++j) {
            int col = nbase + (tx << 2) + j;
            float4 o = *reinterpret_cast<const float4*>(
                dst + (size_t)col * BB + m0 + (ty << 2));
            acc[0][j] = o.x; acc[1][j] = o.y; acc[2][j] = o.z; acc[3][j] = o.w;
        }
    } else {
#pragma unroll
        for (int i = 0; i < 4; ++i)
#pragma unroll
            for (int j = 0; j < 4; ++j) acc[i][j] = 0.0f;
    }

    const float* Arow  = A + (size_t)(m0 + am) * lda + ak;
    const float* Wbase = W + (size_t)koff;

    // prefetch tile 0
    float4 av = *reinterpret_cast<const float4*>(Arow);
    float  bv[4];
#pragma unroll
    for (int q = 0; q < 4; ++q)
        bv[q] = Wbase[(size_t)(nbase + bn + q * 16) * KWID + bk];

    As[0][ak + 0][am] = av.x;
    As[0][ak + 1][am] = av.y;
    As[0][ak + 2][am] = av.z;
    As[0][ak + 3][am] = av.w;
#pragma unroll
    for (int q = 0; q < 4; ++q) Bs[0][bk][bn + q * 16] = bv[q];
    __syncthreads();

    int cur = 0;
    for (int k0 = 0; k0 < K; k0 += 16) {
        const int has_next = (k0 + 16 < K);
        if (has_next) {
            av = *reinterpret_cast<const float4*>(Arow + k0 + 16);
#pragma unroll
            for (int q = 0; q < 4; ++q)
                bv[q] = Wbase[(size_t)(nbase + bn + q * 16) * KWID + k0 + 16 + bk];
        }
#pragma unroll
        for (int kk = 0; kk < 16; ++kk) {
            float4 a4 = *reinterpret_cast<const float4*>(&As[cur][kk][ty << 2]);
            float4 b4 = *reinterpret_cast<const float4*>(&Bs[cur][kk][tx << 2]);
            float a[4] = {a4.x, a4.y, a4.z, a4.w};
            float b[4] = {b4.x, b4.y, b4.z, b4.w};
#pragma unroll
            for (int i = 0; i < 4; ++i)
#pragma unroll
                for (int j = 0; j < 4; ++j)
                    acc[i][j] = fmaf(a[i], b[j], acc[i][j]);
        }
        if (has_next) {
            const int nxt = cur ^ 1;
            As[nxt][ak + 0][am] = av.x;
            As[nxt][ak + 1][am] = av.y;
            As[nxt][ak + 2][am] = av.z;
            As[nxt][ak + 3][am] = av.w;
#pragma unroll
            for (int q = 0; q < 4; ++q) Bs[nxt][bk][bn + q * 16] = bv[q];
            __syncthreads();
            cur = nxt;
        }
    }

#pragma unroll
    for (int j = 0; j < 4; ++j) {
        int col = nbase + (tx << 2) + j;
        float* d = dst + (size_t)col * BB + m0 + (ty << 2);
        float4 v;
        v.x = acc[0][j]; v.y = acc[1][j]; v.z = acc[2][j]; v.w = acc[3][j];
        if (mode == 0) {
            float bv2 = bias[col];
            v.x = __fadd_rn(v.x, bv2);
            v.y = __fadd_rn(v.y, bv2);
            v.z = __fadd_rn(v.z, bv2);
            v.w = __fadd_rn(v.w, bv2);
        }
        *reinterpret_cast<float4*>(d) = v;
    }
}

// ---------------------------------------------------------------------------
// Slot-split sequential sweep (UNCHANGED from R6/R8).
// ---------------------------------------------------------------------------
__global__ void __launch_bounds__(256)
seq_kernel(int base, const float* __restrict__ W, const float* __restrict__ U,
           float* __restrict__ out, float* __restrict__ Lout)
{
    __shared__ __align__(16) float tri[CB][CB + 4]; // tri[i][j], 0 for j<=i
    __shared__ __align__(16) float stg[CB][CB + 4];
    const int tid  = threadIdx.x;
    const int r0   = blockIdx.x * CB;
    const int rl   = tid >> 2;
    const int t    = tid & 3;
    const int r    = r0 + rl;
    const int lane = tid & 31;

#pragma unroll 1
    for (int idx = tid; idx < CB * CB; idx += 256) {
        int i = idx & (CB - 1);
        int j = idx >> 6;
        float v = 0.0f;
        if (j > i) v = W[(size_t)(base + j) * KWID + INF + base + i];
        tri[i][j] = v;
    }
    __syncthreads();

    float ureg[SL], xwreg[SL], accf[SL], logits[SL];
    {
        const float* Urow = U + (size_t)r * OUTF + base + (t << 4);
#pragma unroll
        for (int m = 0; m < SL; m += 4) {
            float4 v = *reinterpret_cast<const float4*>(Urow + m);
            ureg[m] = v.x; ureg[m+1] = v.y; ureg[m+2] = v.z; ureg[m+3] = v.w;
        }
    }
#pragma unroll
    for (int m = 0; m < SL; ++m)
        xwreg[m] = g_XW[(size_t)(base + (t << 4) + m) * BB + r];
    if (base == 0) {
#pragma unroll
        for (int m = 0; m < SL; ++m) accf[m] = 0.0f;
    } else {
#pragma unroll
        for (int m = 0; m < SL; ++m)
            accf[m] = g_D[(size_t)(base + (t << 4) + m) * BB + r];
    }

    unsigned smask = 0u;
    const float* tbase = &tri[0][0] + (t << 4);

#pragma unroll 1
    for (int g = 0; g < TT; ++g) {
        const int src = (lane & ~3) | g;
#pragma unroll
        for (int m = 0; m < SL; ++m) {
            const int i = (g << 4) + m;
            float cand = __fadd_rn(xwreg[m], accf[m]);
            float p    = xla_logistic_f32(cand);
            float sc   = (ureg[m] < p) ? 1.0f : 0.0f;
            float s    = __shfl_sync(0xffffffffu, sc, src);
            if (t == g) {
                logits[m] = cand;
                smask |= (sc != 0.0f ? 1u : 0u) << m;
            }
            const float* trow = tbase + i * (CB + 4);
#pragma unroll
            for (int mm = 0; mm < SL; mm += 4) {
                float4 tv = *reinterpret_cast<const float4*>(trow + mm);
                accf[mm + 0] = fmaf(s, tv.x, accf[mm + 0]);
                accf[mm + 1] = fmaf(s, tv.y, accf[mm + 1]);
                accf[mm + 2] = fmaf(s, tv.z, accf[mm + 2]);
                accf[mm + 3] = fmaf(s, tv.w, accf[mm + 3]);
            }
        }
    }

#pragma unroll
    for (int m = 0; m < SL; m += 4) {
        float4 v; v.x = logits[m]; v.y = logits[m+1]; v.z = logits[m+2]; v.w = logits[m+3];
        *reinterpret_cast<float4*>(&stg[rl][(t << 4) + m]) = v;
    }
    __syncthreads();
#pragma unroll 1
    for (int idx = tid; idx < CB * CB; idx += 256) {
        int rr = idx >> 6, c = idx & (CB - 1);
        Lout[(size_t)(r0 + rr) * OUTF + base + c] = stg[rr][c];
    }
    __syncthreads();
#pragma unroll
    for (int m = 0; m < SL; m += 4) {
        float4 v;
        v.x = (float)((smask >> (m + 0)) & 1u);
        v.y = (float)((smask >> (m + 1)) & 1u);
        v.z = (float)((smask >> (m + 2)) & 1u);
        v.w = (float)((smask >> (m + 3)) & 1u);
        *reinterpret_cast<float4*>(&stg[rl][(t << 4) + m]) = v;
    }
    __syncthreads();
#pragma unroll 1
    for (int idx = tid; idx < CB * CB; idx += 256) {
        int rr = idx >> 6, c = idx & (CB - 1);
        out[(size_t)(r0 + rr) * OUTF + base + c] = stg[rr][c];
    }
}

// ---------------------------------------------------------------------------
// Multi-stream DAG (UNCHANGED from R8):
//  s2: xw blocks 1..15 serially.
//  s0: xw0 -> sweep0 -> updN0 -> sweep1 -> ... -> sweep15
//  s1: updR(k) after sweep(k): D update of blocks k+2..15.
//  Chain order per column preserved: updR(0..m-2) < updN(m-1) via events.
// ---------------------------------------------------------------------------
extern "C" void kernel_launch(void* const* d_in, const int* in_sizes, int n_in,
                              void* d_out, int out_size)
{
    const float* x    = (const float*)d_in[0];
    const float* w    = (const float*)d_in[1];
    const float* bias = (const float*)d_in[2];
    const float* u    = (const float*)d_in[3];
    float* out  = (float*)d_out;
    float* Lout = out + (size_t)BB * OUTF;

    float* xw_ptr;  cudaGetSymbolAddress((void**)&xw_ptr, g_XW);
    float* d_ptr;   cudaGetSymbolAddress((void**)&d_ptr,  g_D);

    cudaStream_t s1, s2;
    cudaStreamCreateWithFlags(&s1, cudaStreamNonBlocking);
    cudaStreamCreateWithFlags(&s2, cudaStreamNonBlocking);

    cudaEvent_t eRoot, eXw[NBLK], eSweep[NBLK], eUpdR[NBLK];
    cudaEventCreateWithFlags(&eRoot, cudaEventDisableTiming);
    for (int i = 0; i < NBLK; ++i) {
        cudaEventCreateWithFlags(&eXw[i],   cudaEventDisableTiming);
        cudaEventCreateWithFlags(&eSweep[i],cudaEventDisableTiming);
        cudaEventCreateWithFlags(&eUpdR[i], cudaEventDisableTiming);
    }

    cudaEventRecord(eRoot, 0);
    cudaStreamWaitEvent(s1, eRoot, 0);
    cudaStreamWaitEvent(s2, eRoot, 0);

    for (int b = 1; b < NBLK; ++b) {
        gemm_kernel<<<dim3(128, 1), 256, 0, s2>>>(x, w, bias, xw_ptr,
                                                  INF, 64 * b, 0, INF, 0);
        cudaEventRecord(eXw[b], s2);
    }

    gemm_kernel<<<dim3(128, 1), 256>>>(x, w, bias, xw_ptr, INF, 0, 0, INF, 0);
    seq_kernel<<<128, 256>>>(0, w, u, out, Lout);
    cudaEventRecord(eSweep[0], 0);

    for (int k = 0; k < NBLK - 1; ++k) {
        if (k <= NBLK - 3) {
            cudaStreamWaitEvent(s1, eSweep[k], 0);
            gemm_kernel<<<dim3(128, NBLK - 2 - k), 256, 0, s1>>>(
                out + 64 * k, w, bias, d_ptr,
                64, 64 * (k + 2), INF + 64 * k, OUTF, (k == 0) ? 1 : 2);
            cudaEventRecord(eUpdR[k], s1);
        }
        if (k >= 1) cudaStreamWaitEvent(0, eUpdR[k - 1], 0);
        gemm_kernel<<<dim3(128, 1), 256>>>(
            out + 64 * k, w, bias, d_ptr,
            64, 64 * (k + 1), INF + 64 * k, OUTF, (k == 0) ? 1 : 2);
        cudaStreamWaitEvent(0, eXw[k + 1], 0);
        seq_kernel<<<128, 256>>>(64 * (k + 1), w, u, out, Lout);
        if (k + 1 < NBLK - 1) cudaEventRecord(eSweep[k + 1], 0);
    }

    for (int i = 0; i < NBLK; ++i) {
        cudaEventDestroy(eXw[i]);
        cudaEventDestroy(eSweep[i]);
        cudaEventDestroy(eUpdR[i]);
    }
    cudaEventDestroy(eRoot);
    cudaStreamDestroy(s1);
    cudaStreamDestroy(s2);
}